// round 5
// baseline (speedup 1.0000x reference)
#include <cuda_runtime.h>
#include <math.h>

// ---------------------------------------------------------------------------
// Problem constants
// ---------------------------------------------------------------------------
#define BB 2
#define SS 512
#define HH 1024
#define NHH 16
#define HD 64
#define TT (BB*SS)          // 1024 tokens
#define EE 32               // experts
#define DD 8                // devices
#define KK 6                // top-k experts
#define KDD 3               // top devices
#define EPD (EE/DD)         // 4 experts per device
#define INTER 1536
#define GU (2*INTER)        // 3072
#define EPSF 1e-5f
#define TOTSEL (TT*KK)      // 6144

// ---------------------------------------------------------------------------
// Scratch (static device globals; no runtime allocation)
// NOTE: these must NEVER be passed as kernel arguments from host code —
// host-side &g_xxx is the host shadow (and ATS makes that silently "work").
// All access is via device-code symbol references (devbuf below).
// ---------------------------------------------------------------------------
__device__ float g_qkv   [TT * 3 * HH];       // 1024 x 3072
__device__ float g_attn  [TT * HH];           // attention output (pre-Wo)
__device__ float g_attno [TT * HH];           // after Wo
__device__ float g_h1    [TT * HH];           // rmsnorm(x + attn)
__device__ float g_gu    [TOTSEL * GU];       // gate/up scratch (max 6144 rows)
__device__ float g_act   [TOTSEL * INTER];    // silu(g)*u scratch
__device__ float g_shared[TT * HH];
__device__ float g_routed[TT * HH];

__device__ int   g_idx   [TT * KK];
__device__ float g_w     [TT * KK];
__device__ int   g_cnt   [EE];
__device__ int   g_off   [EE];
__device__ int   g_cur   [EE];
__device__ int   g_tok   [TOTSEL];
__device__ float g_wt    [TOTSEL];
__device__ float g_probsum[EE];
__device__ float g_devhit [DD];

// Device-side buffer resolver: taking the address HERE (device code) yields
// the correct device address.
#define BUF_QKV    0
#define BUF_ATTN   1
#define BUF_ATTNO  2
#define BUF_H1     3
#define BUF_GU     4
#define BUF_ACT    5
#define BUF_SHARED 6
__device__ __forceinline__ float* devbuf(int id) {
    switch (id) {
        case BUF_QKV:    return g_qkv;
        case BUF_ATTN:   return g_attn;
        case BUF_ATTNO:  return g_attno;
        case BUF_H1:     return g_h1;
        case BUF_GU:     return g_gu;
        case BUF_ACT:    return g_act;
        case BUF_SHARED: return g_shared;
        default:         return g_routed;
    }
}

// ---------------------------------------------------------------------------
// Zero-init (must run every launch; graph replays)
// ---------------------------------------------------------------------------
__global__ void k_zero() {
    int i = blockIdx.x * blockDim.x + threadIdx.x;
    if (i < TT * HH) g_routed[i] = 0.f;
    if (i < EE) { g_cnt[i] = 0; g_probsum[i] = 0.f; }
    if (i < DD) g_devhit[i] = 0.f;
}

// ---------------------------------------------------------------------------
// Generic fp32 SGEMM: C[M,N] = A[M,K] @ B[K,N]   (optionally +=)
// A: external pointer if Aext != nullptr, else devbuf(Aid).
// C: always devbuf(Cid).  B: external (weights from d_in).
// Tile 64x64x16, 256 threads, 4x4 microtile. K % 16 == 0, N % 64 == 0.
// ---------------------------------------------------------------------------
template<bool ACCUM>
__global__ void sgemm_k(const float* __restrict__ Aext, int Aid,
                        const float* __restrict__ B, int Cid,
                        int M, int N, int K)
{
    const float* A = Aext ? Aext : devbuf(Aid);
    float* C = devbuf(Cid);

    __shared__ float As[64][17];
    __shared__ __align__(16) float Bs[16][64];
    const int tid = threadIdx.x;
    const int tx = tid & 15, ty = tid >> 4;
    const int m0 = blockIdx.y * 64, n0 = blockIdx.x * 64;
    float acc[4][4] = {};
    const int ra = tid >> 2, ca = (tid & 3) << 2;
    const int rb = tid >> 4, cb = (tid & 15) << 2;
    for (int k0 = 0; k0 < K; k0 += 16) {
        float4 av = make_float4(0.f, 0.f, 0.f, 0.f);
        int row = m0 + ra;
        if (row < M) av = *(const float4*)(A + (size_t)row * K + k0 + ca);
        As[ra][ca] = av.x; As[ra][ca+1] = av.y; As[ra][ca+2] = av.z; As[ra][ca+3] = av.w;
        *(float4*)&Bs[rb][cb] = *(const float4*)(B + (size_t)(k0 + rb) * N + n0 + cb);
        __syncthreads();
        #pragma unroll
        for (int kk = 0; kk < 16; ++kk) {
            float a[4], b[4];
            #pragma unroll
            for (int i = 0; i < 4; ++i) a[i] = As[ty*4+i][kk];
            #pragma unroll
            for (int j = 0; j < 4; ++j) b[j] = Bs[kk][tx*4+j];
            #pragma unroll
            for (int i = 0; i < 4; ++i)
                #pragma unroll
                for (int j = 0; j < 4; ++j)
                    acc[i][j] = fmaf(a[i], b[j], acc[i][j]);
        }
        __syncthreads();
    }
    #pragma unroll
    for (int i = 0; i < 4; ++i) {
        int row = m0 + ty*4 + i;
        if (row < M) {
            #pragma unroll
            for (int j = 0; j < 4; ++j) {
                int col = n0 + tx*4 + j;
                if (ACCUM) C[(size_t)row * N + col] += acc[i][j];
                else       C[(size_t)row * N + col]  = acc[i][j];
            }
        }
    }
}

// ---------------------------------------------------------------------------
// Grouped gather GEMM: for expert z, gu[off[z]+r] = h1[tok[off[z]+r]] @ Wgu[z]
// N = 3072, K = 1024
// ---------------------------------------------------------------------------
__global__ void k_gemm_gather(const float* __restrict__ Wgu)
{
    const int e = blockIdx.z;
    const int cnt = g_cnt[e];
    const int off = g_off[e];
    const int m0 = blockIdx.y * 64;
    if (m0 >= cnt) return;
    const int n0 = blockIdx.x * 64;
    const float* B = Wgu + (size_t)e * HH * GU;

    __shared__ float As[64][17];
    __shared__ __align__(16) float Bs[16][64];
    const int tid = threadIdx.x;
    const int tx = tid & 15, ty = tid >> 4;
    float acc[4][4] = {};
    const int ra = tid >> 2, ca = (tid & 3) << 2;
    const int rb = tid >> 4, cb = (tid & 15) << 2;
    int tokr = -1;
    if (m0 + ra < cnt) tokr = g_tok[off + m0 + ra];
    for (int k0 = 0; k0 < HH; k0 += 16) {
        float4 av = make_float4(0.f, 0.f, 0.f, 0.f);
        if (tokr >= 0) av = *(const float4*)(g_h1 + (size_t)tokr * HH + k0 + ca);
        As[ra][ca] = av.x; As[ra][ca+1] = av.y; As[ra][ca+2] = av.z; As[ra][ca+3] = av.w;
        *(float4*)&Bs[rb][cb] = *(const float4*)(B + (size_t)(k0 + rb) * GU + n0 + cb);
        __syncthreads();
        #pragma unroll
        for (int kk = 0; kk < 16; ++kk) {
            float a[4], b[4];
            #pragma unroll
            for (int i = 0; i < 4; ++i) a[i] = As[ty*4+i][kk];
            #pragma unroll
            for (int j = 0; j < 4; ++j) b[j] = Bs[kk][tx*4+j];
            #pragma unroll
            for (int i = 0; i < 4; ++i)
                #pragma unroll
                for (int j = 0; j < 4; ++j)
                    acc[i][j] = fmaf(a[i], b[j], acc[i][j]);
        }
        __syncthreads();
    }
    #pragma unroll
    for (int i = 0; i < 4; ++i) {
        int lr = m0 + ty*4 + i;
        if (lr < cnt) {
            #pragma unroll
            for (int j = 0; j < 4; ++j)
                g_gu[(size_t)(off + lr) * GU + n0 + tx*4 + j] = acc[i][j];
        }
    }
}

// ---------------------------------------------------------------------------
// Grouped scatter GEMM: routed[tok] += wt * (act[off[z]+r] @ Wd[z])
// N = 1024, K = 1536
// ---------------------------------------------------------------------------
__global__ void k_gemm_scatter(const float* __restrict__ Wd)
{
    const int e = blockIdx.z;
    const int cnt = g_cnt[e];
    const int off = g_off[e];
    const int m0 = blockIdx.y * 64;
    if (m0 >= cnt) return;
    const int n0 = blockIdx.x * 64;
    const float* B = Wd + (size_t)e * INTER * HH;

    __shared__ float As[64][17];
    __shared__ __align__(16) float Bs[16][64];
    const int tid = threadIdx.x;
    const int tx = tid & 15, ty = tid >> 4;
    float acc[4][4] = {};
    const int ra = tid >> 2, ca = (tid & 3) << 2;
    const int rb = tid >> 4, cb = (tid & 15) << 2;
    for (int k0 = 0; k0 < INTER; k0 += 16) {
        float4 av = make_float4(0.f, 0.f, 0.f, 0.f);
        if (m0 + ra < cnt)
            av = *(const float4*)(g_act + (size_t)(off + m0 + ra) * INTER + k0 + ca);
        As[ra][ca] = av.x; As[ra][ca+1] = av.y; As[ra][ca+2] = av.z; As[ra][ca+3] = av.w;
        *(float4*)&Bs[rb][cb] = *(const float4*)(B + (size_t)(k0 + rb) * HH + n0 + cb);
        __syncthreads();
        #pragma unroll
        for (int kk = 0; kk < 16; ++kk) {
            float a[4], b[4];
            #pragma unroll
            for (int i = 0; i < 4; ++i) a[i] = As[ty*4+i][kk];
            #pragma unroll
            for (int j = 0; j < 4; ++j) b[j] = Bs[kk][tx*4+j];
            #pragma unroll
            for (int i = 0; i < 4; ++i)
                #pragma unroll
                for (int j = 0; j < 4; ++j)
                    acc[i][j] = fmaf(a[i], b[j], acc[i][j]);
        }
        __syncthreads();
    }
    #pragma unroll
    for (int i = 0; i < 4; ++i) {
        int lr = m0 + ty*4 + i;
        if (lr < cnt) {
            int token = g_tok[off + lr];
            float wt  = g_wt[off + lr];
            #pragma unroll
            for (int j = 0; j < 4; ++j)
                atomicAdd(&g_routed[(size_t)token * HH + n0 + tx*4 + j], wt * acc[i][j]);
        }
    }
}

// ---------------------------------------------------------------------------
// Attention: one warp per query. S=512, HD=64.
// grid (S/4, NH, B), block 128
// ---------------------------------------------------------------------------
__global__ void k_attn()
{
    __shared__ float sc[4][SS];
    const int w = threadIdx.x >> 5;
    const int lane = threadIdx.x & 31;
    const int q = blockIdx.x * 4 + w;
    const int h = blockIdx.y;
    const int b = blockIdx.z;
    const int d0 = 2 * lane;

    const size_t qp = ((size_t)(b * SS + q) * 3 * HH) + h * HD;
    float2 qv = *(const float2*)(g_qkv + qp + d0);

    for (int k = 0; k < SS; ++k) {
        const size_t kp = ((size_t)(b * SS + k) * 3 * HH) + HH + h * HD;
        float2 kv = *(const float2*)(g_qkv + kp + d0);
        float s = qv.x * kv.x + qv.y * kv.y;
        #pragma unroll
        for (int o = 16; o > 0; o >>= 1) s += __shfl_xor_sync(0xffffffffu, s, o);
        if (lane == 0) sc[w][k] = s * 0.125f;   // 1/sqrt(64)
    }
    __syncwarp();
    float m = -INFINITY;
    for (int k = lane; k < SS; k += 32) m = fmaxf(m, sc[w][k]);
    #pragma unroll
    for (int o = 16; o > 0; o >>= 1) m = fmaxf(m, __shfl_xor_sync(0xffffffffu, m, o));
    float sum = 0.f;
    for (int k = lane; k < SS; k += 32) {
        float p = expf(sc[w][k] - m);
        sc[w][k] = p;
        sum += p;
    }
    #pragma unroll
    for (int o = 16; o > 0; o >>= 1) sum += __shfl_xor_sync(0xffffffffu, sum, o);
    float inv = 1.f / sum;
    __syncwarp();
    float a0 = 0.f, a1 = 0.f;
    for (int k = 0; k < SS; ++k) {
        float p = sc[w][k];
        const size_t vp = ((size_t)(b * SS + k) * 3 * HH) + 2 * HH + h * HD;
        float2 vv = *(const float2*)(g_qkv + vp + d0);
        a0 = fmaf(p, vv.x, a0);
        a1 = fmaf(p, vv.y, a1);
    }
    float* op = g_attn + (size_t)(b * SS + q) * HH + h * HD;
    op[d0]     = a0 * inv;
    op[d0 + 1] = a1 * inv;
}

// ---------------------------------------------------------------------------
// h1 = rmsnorm(x + attno).  One block per row.
// ---------------------------------------------------------------------------
__global__ void k_addrms(const float* __restrict__ x)
{
    __shared__ float ys[HH];
    __shared__ float red[256];
    const int r = blockIdx.x;
    float ss = 0.f;
    for (int i = threadIdx.x; i < HH; i += 256) {
        float v = x[(size_t)r * HH + i] + g_attno[(size_t)r * HH + i];
        ys[i] = v;
        ss += v * v;
    }
    red[threadIdx.x] = ss;
    __syncthreads();
    for (int s = 128; s > 0; s >>= 1) {
        if (threadIdx.x < s) red[threadIdx.x] += red[threadIdx.x + s];
        __syncthreads();
    }
    float scale = rsqrtf(red[0] / (float)HH + EPSF);
    for (int i = threadIdx.x; i < HH; i += 256)
        g_h1[(size_t)r * HH + i] = ys[i] * scale;
}

// ---------------------------------------------------------------------------
// SwiGLU activation: act[r, j] = silu(gu[r, j]) * gu[r, INTER + j]
// ---------------------------------------------------------------------------
__global__ void k_act(int rows)
{
    const long long n = (long long)rows * INTER;
    for (long long i = (long long)blockIdx.x * blockDim.x + threadIdx.x;
         i < n; i += (long long)gridDim.x * blockDim.x) {
        long long r = i / INTER;
        long long j = i % INTER;
        float g = g_gu[r * GU + j];
        float u = g_gu[r * GU + INTER + j];
        float s = g / (1.f + expf(-g));
        g_act[i] = s * u;
    }
}

// ---------------------------------------------------------------------------
// Router: one warp per token.
// ---------------------------------------------------------------------------
__global__ void k_route(const float* __restrict__ Wr)
{
    __shared__ float xr[HH];
    __shared__ float logit_s[EE];
    __shared__ float probs[EE];
    const int t = blockIdx.x;
    const int lane = threadIdx.x;

    for (int i = lane; i < HH; i += 32) xr[i] = g_h1[(size_t)t * HH + i];
    __syncwarp();
    float acc = 0.f;
    for (int hh = 0; hh < HH; ++hh)
        acc = fmaf(xr[hh], Wr[(size_t)hh * EE + lane], acc);
    logit_s[lane] = acc;
    __syncwarp();

    if (lane == 0) {
        float m = -INFINITY;
        for (int e = 0; e < EE; ++e) m = fmaxf(m, logit_s[e]);
        float s = 0.f;
        for (int e = 0; e < EE; ++e) { float p = expf(logit_s[e] - m); probs[e] = p; s += p; }
        float inv = 1.f / s;
        for (int e = 0; e < EE; ++e) probs[e] *= inv;

        // device scores
        float dev[DD];
        for (int d = 0; d < DD; ++d)
            dev[d] = probs[4*d] + probs[4*d+1] + probs[4*d+2] + probs[4*d+3];
        // top-3 devices (strict >, ascending scan = lowest-index tie-break, like jax)
        bool devsel[DD];
        for (int d = 0; d < DD; ++d) devsel[d] = false;
        for (int r = 0; r < KDD; ++r) {
            float best = -INFINITY; int bi = -1;
            for (int d = 0; d < DD; ++d)
                if (!devsel[d] && dev[d] > best) { best = dev[d]; bi = d; }
            devsel[bi] = true;
        }
        // top-6 experts among allowed
        int idx6[KK]; float w6[KK];
        bool taken[EE];
        for (int e = 0; e < EE; ++e) taken[e] = false;
        for (int r = 0; r < KK; ++r) {
            float best = -INFINITY; int bi = -1;
            for (int e = 0; e < EE; ++e)
                if (devsel[e >> 2] && !taken[e] && probs[e] > best) { best = probs[e]; bi = e; }
            taken[bi] = true; idx6[r] = bi; w6[r] = best;
        }
        // softmax over selected weights
        float wm = -INFINITY;
        for (int r = 0; r < KK; ++r) wm = fmaxf(wm, w6[r]);
        float ws = 0.f;
        for (int r = 0; r < KK; ++r) { w6[r] = expf(w6[r] - wm); ws += w6[r]; }
        float winv = 1.f / ws;
        for (int r = 0; r < KK; ++r) {
            w6[r] *= winv;
            g_idx[t * KK + r] = idx6[r];
            g_w[t * KK + r] = w6[r];
            atomicAdd(&g_cnt[idx6[r]], 1);
        }
        // device hit indicator
        bool hit[DD];
        for (int d = 0; d < DD; ++d) hit[d] = false;
        for (int r = 0; r < KK; ++r) hit[idx6[r] >> 2] = true;
        for (int d = 0; d < DD; ++d)
            if (hit[d]) atomicAdd(&g_devhit[d], 1.0f);
    }
    __syncwarp();
    atomicAdd(&g_probsum[lane], probs[lane]);
}

// ---------------------------------------------------------------------------
// Exclusive scan over expert counts; init cursors.
// ---------------------------------------------------------------------------
__global__ void k_scan()
{
    int acc = 0;
    for (int e = 0; e < EE; ++e) {
        g_off[e] = acc;
        g_cur[e] = acc;
        acc += g_cnt[e];
    }
}

// Fill per-expert compacted token lists.
__global__ void k_build()
{
    int i = blockIdx.x * blockDim.x + threadIdx.x;
    if (i >= TOTSEL) return;
    int e = g_idx[i];
    int pos = atomicAdd(&g_cur[e], 1);
    g_tok[pos] = i / KK;
    g_wt[pos] = g_w[i];
}

// ---------------------------------------------------------------------------
// Final: out = rmsnorm(h1 + shared + routed)
// ---------------------------------------------------------------------------
__global__ void k_final(float* __restrict__ out)
{
    __shared__ float ys[HH];
    __shared__ float red[256];
    const int r = blockIdx.x;
    float ss = 0.f;
    for (int i = threadIdx.x; i < HH; i += 256) {
        size_t p = (size_t)r * HH + i;
        float v = g_h1[p] + g_shared[p] + g_routed[p];
        ys[i] = v;
        ss += v * v;
    }
    red[threadIdx.x] = ss;
    __syncthreads();
    for (int s = 128; s > 0; s >>= 1) {
        if (threadIdx.x < s) red[threadIdx.x] += red[threadIdx.x + s];
        __syncthreads();
    }
    float scale = rsqrtf(red[0] / (float)HH + EPSF);
    for (int i = threadIdx.x; i < HH; i += 256)
        out[(size_t)r * HH + i] = ys[i] * scale;
}

// ---------------------------------------------------------------------------
// Aux loss scalar.
// ---------------------------------------------------------------------------
__global__ void k_aux(float* __restrict__ dst)
{
    float f_i[EE], P_i[EE];
    for (int e = 0; e < EE; ++e) {
        f_i[e] = (float)g_cnt[e] / ((float)TOTSEL + 1e-10f);
        P_i[e] = g_probsum[e] / (float)TT;
    }
    float eb = 0.f;
    for (int e = 0; e < EE; ++e) eb += f_i[e] * P_i[e];
    float expert_bal = fminf(eb * 0.003f, 10.f);

    float db = 0.f, cb = 0.f;
    for (int d = 0; d < DD; ++d) {
        float df = 0.f, dP = 0.f;
        for (int j = 0; j < EPD; ++j) { df += f_i[4*d + j]; dP += P_i[4*d + j]; }
        df *= 0.25f;
        db += df * dP;
        float fc = g_devhit[d] / ((float)(TT * KDD) + 1e-10f);
        cb += fc * dP;
    }
    float device_bal = fminf(db * 0.05f, 10.f);
    float comm_bal   = fminf(cb * 0.02f, 10.f);
    *dst = expert_bal + device_bal + comm_bal;
}

// ---------------------------------------------------------------------------
// Launch.  Only genuine device pointers (d_in/d_out) cross the host/device
// boundary; scratch buffers are selected by integer ID, resolved in device
// code via devbuf().
// ---------------------------------------------------------------------------
extern "C" void kernel_launch(void* const* d_in, const int* in_sizes, int n_in,
                              void* d_out, int out_size)
{
    const float* x     = (const float*)d_in[0];
    const float* Wqkv  = (const float*)d_in[1];
    const float* Wo    = (const float*)d_in[2];
    const float* Wgu_s = (const float*)d_in[3];
    const float* Wd_s  = (const float*)d_in[4];
    const float* Wr    = (const float*)d_in[5];
    const float* Wgu   = (const float*)d_in[6];
    const float* Wd    = (const float*)d_in[7];
    float* out = (float*)d_out;

    k_zero<<<(TT * HH + 255) / 256, 256>>>();

    // QKV projection: (1024 x 1024) @ (1024 x 3072) -> g_qkv
    sgemm_k<false><<<dim3(48, 16), 256>>>(x, -1, Wqkv, BUF_QKV, TT, 3 * HH, HH);

    // Attention
    k_attn<<<dim3(SS / 4, NHH, BB), 128>>>();

    // Output projection: g_attn @ Wo -> g_attno
    sgemm_k<false><<<dim3(16, 16), 256>>>(nullptr, BUF_ATTN, Wo, BUF_ATTNO, TT, HH, HH);

    // h1 = rmsnorm(x + attn)
    k_addrms<<<TT, 256>>>(x);

    // Shared expert 0
    sgemm_k<false><<<dim3(48, 16), 256>>>(nullptr, BUF_H1, Wgu_s, BUF_GU, TT, GU, HH);
    k_act<<<1024, 256>>>(TT);
    sgemm_k<false><<<dim3(16, 16), 256>>>(nullptr, BUF_ACT, Wd_s, BUF_SHARED, TT, HH, INTER);

    // Shared expert 1 (accumulate)
    sgemm_k<false><<<dim3(48, 16), 256>>>(nullptr, BUF_H1, Wgu_s + (size_t)HH * GU, BUF_GU, TT, GU, HH);
    k_act<<<1024, 256>>>(TT);
    sgemm_k<true><<<dim3(16, 16), 256>>>(nullptr, BUF_ACT, Wd_s + (size_t)INTER * HH, BUF_SHARED, TT, HH, INTER);

    // Routing
    k_route<<<TT, 32>>>(Wr);
    k_scan<<<1, 1>>>();
    k_build<<<TOTSEL / 256, 256>>>();

    // Routed experts (grouped, gathered)
    k_gemm_gather<<<dim3(GU / 64, 16, EE), 256>>>(Wgu);
    k_act<<<4096, 256>>>(TOTSEL);
    k_gemm_scatter<<<dim3(HH / 64, 16, EE), 256>>>(Wd);

    // Final norm + output
    k_final<<<TT, 256>>>(out);

    if (out_size > TT * HH)
        k_aux<<<1, 1>>>(out + TT * HH);
}

// round 12
// speedup vs baseline: 1.8685x; 1.8685x over previous
#include <cuda_runtime.h>
#include <cuda_bf16.h>
#include <stdint.h>
#include <math.h>

// ---------------------------------------------------------------------------
// Problem constants
// ---------------------------------------------------------------------------
#define BB 2
#define SS 512
#define HH 1024
#define NHH 16
#define HD 64
#define TT (BB*SS)          // 1024 tokens
#define EE 32               // experts
#define DD 8                // devices
#define KK 6                // top-k experts
#define KDD 3               // top devices
#define EPD (EE/DD)         // 4 experts per device
#define INTER 1536
#define GU (2*INTER)        // 3072
#define EPSF 1e-5f
#define TOTSEL (TT*KK)      // 6144

// ---------------------------------------------------------------------------
// Scratch (static device globals; accessed ONLY by device-code symbol refs)
// ---------------------------------------------------------------------------
__device__ float g_qkv   [TT * 3 * HH];
__device__ float g_attn  [TT * HH];
__device__ float g_attno [TT * HH];
__device__ float g_h1    [TT * HH];
__device__ float g_gu    [TOTSEL * GU];
__device__ float g_act   [TOTSEL * INTER];
__device__ float g_shared[TT * HH];
__device__ float g_routed[TT * HH];

__device__ int   g_idx   [TT * KK];
__device__ float g_w     [TT * KK];
__device__ int   g_cnt   [EE];
__device__ int   g_off   [EE];
__device__ int   g_cur   [EE];
__device__ int   g_tok   [TOTSEL];
__device__ float g_wt    [TOTSEL];
__device__ float g_probsum[EE];
__device__ float g_devhit [DD];

#define BUF_QKV    0
#define BUF_ATTN   1
#define BUF_ATTNO  2
#define BUF_H1     3
#define BUF_GU     4
#define BUF_ACT    5
#define BUF_SHARED 6
__device__ __forceinline__ float* devbuf(int id) {
    switch (id) {
        case BUF_QKV:    return g_qkv;
        case BUF_ATTN:   return g_attn;
        case BUF_ATTNO:  return g_attno;
        case BUF_H1:     return g_h1;
        case BUF_GU:     return g_gu;
        case BUF_ACT:    return g_act;
        case BUF_SHARED: return g_shared;
        default:         return g_routed;
    }
}

// ---------------------------------------------------------------------------
// PTX helpers (base-ISA only: ldmatrix + mma.sync; NO tcgen05 — not available
// at the compute_103 PTX target this harness compiles with)
// ---------------------------------------------------------------------------
__device__ __forceinline__ uint32_t smem_u32(const void* p) {
    uint32_t a;
    asm("{ .reg .u64 t; cvta.to.shared.u64 t, %1; cvt.u32.u64 %0, t; }" : "=r"(a) : "l"(p));
    return a;
}
__device__ __forceinline__ void ldsm_x4(uint32_t& r0, uint32_t& r1, uint32_t& r2, uint32_t& r3,
                                        uint32_t addr) {
    asm volatile("ldmatrix.sync.aligned.m8n8.x4.shared.b16 {%0,%1,%2,%3}, [%4];"
                 : "=r"(r0), "=r"(r1), "=r"(r2), "=r"(r3) : "r"(addr));
}
__device__ __forceinline__ void ldsm_x4_t(uint32_t& r0, uint32_t& r1, uint32_t& r2, uint32_t& r3,
                                          uint32_t addr) {
    asm volatile("ldmatrix.sync.aligned.m8n8.x4.trans.shared.b16 {%0,%1,%2,%3}, [%4];"
                 : "=r"(r0), "=r"(r1), "=r"(r2), "=r"(r3) : "r"(addr));
}
__device__ __forceinline__ void mma_bf16(float* c, const uint32_t* a, const uint32_t* b) {
    asm volatile("mma.sync.aligned.m16n8k16.row.col.f32.bf16.bf16.f32 "
                 "{%0,%1,%2,%3}, {%4,%5,%6,%7}, {%8,%9}, {%0,%1,%2,%3};"
                 : "+f"(c[0]), "+f"(c[1]), "+f"(c[2]), "+f"(c[3])
                 : "r"(a[0]), "r"(a[1]), "r"(a[2]), "r"(a[3]), "r"(b[0]), "r"(b[1]));
}
// pack (lo_elem, hi_elem) -> bf16x2; first PTX source goes to the HIGH half
__device__ __forceinline__ uint32_t pk_bf16x2(float lo, float hi) {
    uint32_t r;
    asm("cvt.rn.bf16x2.f32 %0, %1, %2;" : "=r"(r) : "f"(hi), "f"(lo));
    return r;
}
__device__ __forceinline__ float bf16_round(float x) {
    return __bfloat162float(__float2bfloat16(x));
}

// ---------------------------------------------------------------------------
// bf16-split tensor-core GEMM:  C[M,N] = A[M,K] @ W[K,N]  (fp32 in/out)
//   A@B ~= Ahi*Bhi + Alo*Bhi + Ahi*Blo  (fp32 accumulate, err ~2^-18)
// MODE 0: plain (A = Aext or devbuf(Aid), C = devbuf(Cid))
// MODE 1: gather (A rows = g_h1[g_tok[off+r]], C = g_gu rows off+r)
// MODE 2: scatter (A rows = g_act[off+r], C = atomicAdd g_routed, weighted)
// Tile 128x128x32, 256 threads (8 warps as 4x2), warp = 32x64.
// ---------------------------------------------------------------------------
#define BM 128
#define BN 128
#define BK 32
#define ASTR (BK + 8)       // 40
#define BSTR (BN + 8)       // 136

template<int MODE, bool ACCUM>
__global__ __launch_bounds__(256, 1)
void mma_gemm(const float* __restrict__ Aext, int Aid, int Cid,
              const float* __restrict__ W, long long Wstride,
              int K, int N)
{
    __shared__ __align__(16) __nv_bfloat16 As_hi[BM][ASTR];
    __shared__ __align__(16) __nv_bfloat16 As_lo[BM][ASTR];
    __shared__ __align__(16) __nv_bfloat16 Bs_hi[BK][BSTR];
    __shared__ __align__(16) __nv_bfloat16 Bs_lo[BK][BSTR];

    const int tid  = threadIdx.x;
    const int lane = tid & 31;
    const int warp = tid >> 5;
    const int wm = warp >> 1;          // 0..3
    const int wn = warp & 1;           // 0..1
    const int m0 = blockIdx.y * BM;
    const int n0 = blockIdx.x * BN;
    const int z  = blockIdx.z;

    int cnt = 0, off = 0;
    if (MODE != 0) {
        cnt = g_cnt[z];
        off = g_off[z];
        if (m0 >= cnt) return;
    }
    const float* Wb = W + (size_t)z * (size_t)Wstride;
    const float* Abase = (MODE == 0) ? (Aext ? Aext : devbuf(Aid)) : nullptr;

    // per-thread fill coordinates (4 chunks each for A and B)
    int arow[4], akc[4], brow[4], bnc[4];
    #pragma unroll
    for (int i = 0; i < 4; ++i) {
        int ca = tid + i * 256;        // 0..1023 over 128x8 float4 chunks
        arow[i] = ca >> 3;
        akc[i]  = (ca & 7) * 4;
        brow[i] = ca >> 5;             // k row 0..31
        bnc[i]  = (ca & 31) * 4;       // n 0..124
    }
    // A row source pointers (gather resolved once)
    const float* aptr[4];
    #pragma unroll
    for (int i = 0; i < 4; ++i) {
        int lr = m0 + arow[i];
        if (MODE == 0)      aptr[i] = Abase + (size_t)lr * (size_t)K;
        else if (MODE == 1) aptr[i] = (lr < cnt) ? g_h1 + (size_t)g_tok[off + lr] * HH : nullptr;
        else                aptr[i] = (lr < cnt) ? g_act + (size_t)(off + lr) * (size_t)K : nullptr;
    }

    float acc[2][8][4];
    #pragma unroll
    for (int t = 0; t < 2; ++t)
        #pragma unroll
        for (int j = 0; j < 8; ++j)
            #pragma unroll
            for (int c = 0; c < 4; ++c) acc[t][j][c] = 0.f;

    float4 av[4], bv[4];
    const int niter = K / BK;

    // prologue: load k-tile 0
    #pragma unroll
    for (int i = 0; i < 4; ++i) {
        av[i] = aptr[i] ? *(const float4*)(aptr[i] + akc[i]) : make_float4(0.f,0.f,0.f,0.f);
        bv[i] = *(const float4*)(Wb + (size_t)brow[i] * (size_t)N + n0 + bnc[i]);
    }

    for (int it = 0; it < niter; ++it) {
        // ---- store staged tile to smem (convert fp32 -> hi/lo bf16) ----
        #pragma unroll
        for (int i = 0; i < 4; ++i) {
            float hx = bf16_round(av[i].x), hy = bf16_round(av[i].y);
            float hz = bf16_round(av[i].z), hw = bf16_round(av[i].w);
            *(uint2*)&As_hi[arow[i]][akc[i]] =
                make_uint2(pk_bf16x2(av[i].x, av[i].y), pk_bf16x2(av[i].z, av[i].w));
            *(uint2*)&As_lo[arow[i]][akc[i]] =
                make_uint2(pk_bf16x2(av[i].x - hx, av[i].y - hy),
                           pk_bf16x2(av[i].z - hz, av[i].w - hw));
            float gx = bf16_round(bv[i].x), gy = bf16_round(bv[i].y);
            float gz = bf16_round(bv[i].z), gw = bf16_round(bv[i].w);
            *(uint2*)&Bs_hi[brow[i]][bnc[i]] =
                make_uint2(pk_bf16x2(bv[i].x, bv[i].y), pk_bf16x2(bv[i].z, bv[i].w));
            *(uint2*)&Bs_lo[brow[i]][bnc[i]] =
                make_uint2(pk_bf16x2(bv[i].x - gx, bv[i].y - gy),
                           pk_bf16x2(bv[i].z - gz, bv[i].w - gw));
        }
        __syncthreads();

        // ---- prefetch next k-tile (overlaps with mma phase) ----
        if (it + 1 < niter) {
            const int k0 = (it + 1) * BK;
            #pragma unroll
            for (int i = 0; i < 4; ++i) {
                av[i] = aptr[i] ? *(const float4*)(aptr[i] + k0 + akc[i])
                                : make_float4(0.f,0.f,0.f,0.f);
                bv[i] = *(const float4*)(Wb + (size_t)(k0 + brow[i]) * (size_t)N + n0 + bnc[i]);
            }
        }

        // ---- compute: 2 k16 steps ----
        #pragma unroll
        for (int s = 0; s < 2; ++s) {
            uint32_t ah[2][4], al[2][4], bh[4][4], bl[4][4];
            const int ar = (lane & 15);
            const int ac = s * 16 + (lane >> 4) * 8;
            #pragma unroll
            for (int t = 0; t < 2; ++t) {
                uint32_t ad = smem_u32(&As_hi[wm * 32 + t * 16 + ar][ac]);
                ldsm_x4(ah[t][0], ah[t][1], ah[t][2], ah[t][3], ad);
                uint32_t ad2 = smem_u32(&As_lo[wm * 32 + t * 16 + ar][ac]);
                ldsm_x4(al[t][0], al[t][1], al[t][2], al[t][3], ad2);
            }
            const int br = s * 16 + (lane & 15);
            #pragma unroll
            for (int g = 0; g < 4; ++g) {
                int bc = wn * 64 + g * 16 + (lane >> 4) * 8;
                uint32_t bd = smem_u32(&Bs_hi[br][bc]);
                ldsm_x4_t(bh[g][0], bh[g][1], bh[g][2], bh[g][3], bd);
                uint32_t bd2 = smem_u32(&Bs_lo[br][bc]);
                ldsm_x4_t(bl[g][0], bl[g][1], bl[g][2], bl[g][3], bd2);
            }
            #pragma unroll
            for (int t = 0; t < 2; ++t) {
                #pragma unroll
                for (int j = 0; j < 8; ++j) {
                    const int g = j >> 1;
                    const int sel = (j & 1) * 2;
                    mma_bf16(acc[t][j], ah[t], &bh[g][sel]);   // hi*hi
                    mma_bf16(acc[t][j], al[t], &bh[g][sel]);   // lo*hi
                    mma_bf16(acc[t][j], ah[t], &bl[g][sel]);   // hi*lo
                }
            }
        }
        __syncthreads();
    }

    // ---- epilogue ----
    const int gq = lane >> 2;          // 0..7
    const int tq = lane & 3;           // 0..3
    #pragma unroll
    for (int t = 0; t < 2; ++t) {
        const int rr0 = wm * 32 + t * 16 + gq;     // tile-relative rows
        const int rr1 = rr0 + 8;
        #pragma unroll
        for (int j = 0; j < 8; ++j) {
            const int col = n0 + wn * 64 + j * 8 + tq * 2;
            float d0 = acc[t][j][0], d1 = acc[t][j][1];
            float d2 = acc[t][j][2], d3 = acc[t][j][3];
            if (MODE == 0) {
                float* C = devbuf(Cid);
                float2* p0 = (float2*)&C[(size_t)(m0 + rr0) * (size_t)N + col];
                float2* p1 = (float2*)&C[(size_t)(m0 + rr1) * (size_t)N + col];
                if (ACCUM) {
                    float2 o0 = *p0, o1 = *p1;
                    *p0 = make_float2(o0.x + d0, o0.y + d1);
                    *p1 = make_float2(o1.x + d2, o1.y + d3);
                } else {
                    *p0 = make_float2(d0, d1);
                    *p1 = make_float2(d2, d3);
                }
            } else if (MODE == 1) {
                if (m0 + rr0 < cnt)
                    *(float2*)&g_gu[(size_t)(off + m0 + rr0) * (size_t)N + col] = make_float2(d0, d1);
                if (m0 + rr1 < cnt)
                    *(float2*)&g_gu[(size_t)(off + m0 + rr1) * (size_t)N + col] = make_float2(d2, d3);
            } else {
                if (m0 + rr0 < cnt) {
                    int token = g_tok[off + m0 + rr0];
                    float wt  = g_wt[off + m0 + rr0];
                    atomicAdd(&g_routed[(size_t)token * HH + col],     wt * d0);
                    atomicAdd(&g_routed[(size_t)token * HH + col + 1], wt * d1);
                }
                if (m0 + rr1 < cnt) {
                    int token = g_tok[off + m0 + rr1];
                    float wt  = g_wt[off + m0 + rr1];
                    atomicAdd(&g_routed[(size_t)token * HH + col],     wt * d2);
                    atomicAdd(&g_routed[(size_t)token * HH + col + 1], wt * d3);
                }
            }
        }
    }
}

// ---------------------------------------------------------------------------
// Zero-init (graph replays)
// ---------------------------------------------------------------------------
__global__ void k_zero() {
    int i = blockIdx.x * blockDim.x + threadIdx.x;
    if (i < TT * HH) g_routed[i] = 0.f;
    if (i < EE) { g_cnt[i] = 0; g_probsum[i] = 0.f; }
    if (i < DD) g_devhit[i] = 0.f;
}

// ---------------------------------------------------------------------------
// Attention: one warp per query. S=512, HD=64.
// ---------------------------------------------------------------------------
__global__ void k_attn()
{
    __shared__ float sc[4][SS];
    const int w = threadIdx.x >> 5;
    const int lane = threadIdx.x & 31;
    const int q = blockIdx.x * 4 + w;
    const int h = blockIdx.y;
    const int b = blockIdx.z;
    const int d0 = 2 * lane;

    const size_t qp = ((size_t)(b * SS + q) * 3 * HH) + h * HD;
    float2 qv = *(const float2*)(g_qkv + qp + d0);

    for (int k = 0; k < SS; ++k) {
        const size_t kp = ((size_t)(b * SS + k) * 3 * HH) + HH + h * HD;
        float2 kv = *(const float2*)(g_qkv + kp + d0);
        float s = qv.x * kv.x + qv.y * kv.y;
        #pragma unroll
        for (int o = 16; o > 0; o >>= 1) s += __shfl_xor_sync(0xffffffffu, s, o);
        if (lane == 0) sc[w][k] = s * 0.125f;
    }
    __syncwarp();
    float m = -INFINITY;
    for (int k = lane; k < SS; k += 32) m = fmaxf(m, sc[w][k]);
    #pragma unroll
    for (int o = 16; o > 0; o >>= 1) m = fmaxf(m, __shfl_xor_sync(0xffffffffu, m, o));
    float sum = 0.f;
    for (int k = lane; k < SS; k += 32) {
        float p = expf(sc[w][k] - m);
        sc[w][k] = p;
        sum += p;
    }
    #pragma unroll
    for (int o = 16; o > 0; o >>= 1) sum += __shfl_xor_sync(0xffffffffu, sum, o);
    float inv = 1.f / sum;
    __syncwarp();
    float a0 = 0.f, a1 = 0.f;
    for (int k = 0; k < SS; ++k) {
        float p = sc[w][k];
        const size_t vp = ((size_t)(b * SS + k) * 3 * HH) + 2 * HH + h * HD;
        float2 vv = *(const float2*)(g_qkv + vp + d0);
        a0 = fmaf(p, vv.x, a0);
        a1 = fmaf(p, vv.y, a1);
    }
    float* op = g_attn + (size_t)(b * SS + q) * HH + h * HD;
    op[d0]     = a0 * inv;
    op[d0 + 1] = a1 * inv;
}

// ---------------------------------------------------------------------------
// h1 = rmsnorm(x + attno)
// ---------------------------------------------------------------------------
__global__ void k_addrms(const float* __restrict__ x)
{
    __shared__ float ys[HH];
    __shared__ float red[256];
    const int r = blockIdx.x;
    float ss = 0.f;
    for (int i = threadIdx.x; i < HH; i += 256) {
        float v = x[(size_t)r * HH + i] + g_attno[(size_t)r * HH + i];
        ys[i] = v;
        ss += v * v;
    }
    red[threadIdx.x] = ss;
    __syncthreads();
    for (int s = 128; s > 0; s >>= 1) {
        if (threadIdx.x < s) red[threadIdx.x] += red[threadIdx.x + s];
        __syncthreads();
    }
    float scale = rsqrtf(red[0] / (float)HH + EPSF);
    for (int i = threadIdx.x; i < HH; i += 256)
        g_h1[(size_t)r * HH + i] = ys[i] * scale;
}

// ---------------------------------------------------------------------------
// SwiGLU activation
// ---------------------------------------------------------------------------
__global__ void k_act(int rows)
{
    const long long n = (long long)rows * INTER;
    for (long long i = (long long)blockIdx.x * blockDim.x + threadIdx.x;
         i < n; i += (long long)gridDim.x * blockDim.x) {
        long long r = i / INTER;
        long long j = i % INTER;
        float g = g_gu[r * GU + j];
        float u = g_gu[r * GU + INTER + j];
        float s = g / (1.f + expf(-g));
        g_act[i] = s * u;
    }
}

// ---------------------------------------------------------------------------
// Router: one warp per token.
// ---------------------------------------------------------------------------
__global__ void k_route(const float* __restrict__ Wr)
{
    __shared__ float xr[HH];
    __shared__ float logit_s[EE];
    __shared__ float probs[EE];
    const int t = blockIdx.x;
    const int lane = threadIdx.x;

    for (int i = lane; i < HH; i += 32) xr[i] = g_h1[(size_t)t * HH + i];
    __syncwarp();
    float acc = 0.f;
    for (int hh = 0; hh < HH; ++hh)
        acc = fmaf(xr[hh], Wr[(size_t)hh * EE + lane], acc);
    logit_s[lane] = acc;
    __syncwarp();

    if (lane == 0) {
        float m = -INFINITY;
        for (int e = 0; e < EE; ++e) m = fmaxf(m, logit_s[e]);
        float s = 0.f;
        for (int e = 0; e < EE; ++e) { float p = expf(logit_s[e] - m); probs[e] = p; s += p; }
        float inv = 1.f / s;
        for (int e = 0; e < EE; ++e) probs[e] *= inv;

        float dev[DD];
        for (int d = 0; d < DD; ++d)
            dev[d] = probs[4*d] + probs[4*d+1] + probs[4*d+2] + probs[4*d+3];
        bool devsel[DD];
        for (int d = 0; d < DD; ++d) devsel[d] = false;
        for (int rr = 0; rr < KDD; ++rr) {
            float best = -INFINITY; int bi = -1;
            for (int d = 0; d < DD; ++d)
                if (!devsel[d] && dev[d] > best) { best = dev[d]; bi = d; }
            devsel[bi] = true;
        }
        int idx6[KK]; float w6[KK];
        bool taken[EE];
        for (int e = 0; e < EE; ++e) taken[e] = false;
        for (int rr = 0; rr < KK; ++rr) {
            float best = -INFINITY; int bi = -1;
            for (int e = 0; e < EE; ++e)
                if (devsel[e >> 2] && !taken[e] && probs[e] > best) { best = probs[e]; bi = e; }
            taken[bi] = true; idx6[rr] = bi; w6[rr] = best;
        }
        float wm = -INFINITY;
        for (int rr = 0; rr < KK; ++rr) wm = fmaxf(wm, w6[rr]);
        float ws = 0.f;
        for (int rr = 0; rr < KK; ++rr) { w6[rr] = expf(w6[rr] - wm); ws += w6[rr]; }
        float winv = 1.f / ws;
        for (int rr = 0; rr < KK; ++rr) {
            w6[rr] *= winv;
            g_idx[t * KK + rr] = idx6[rr];
            g_w[t * KK + rr] = w6[rr];
            atomicAdd(&g_cnt[idx6[rr]], 1);
        }
        bool hit[DD];
        for (int d = 0; d < DD; ++d) hit[d] = false;
        for (int rr = 0; rr < KK; ++rr) hit[idx6[rr] >> 2] = true;
        for (int d = 0; d < DD; ++d)
            if (hit[d]) atomicAdd(&g_devhit[d], 1.0f);
    }
    __syncwarp();
    atomicAdd(&g_probsum[lane], probs[lane]);
}

__global__ void k_scan()
{
    int acc = 0;
    for (int e = 0; e < EE; ++e) {
        g_off[e] = acc;
        g_cur[e] = acc;
        acc += g_cnt[e];
    }
}

__global__ void k_build()
{
    int i = blockIdx.x * blockDim.x + threadIdx.x;
    if (i >= TOTSEL) return;
    int e = g_idx[i];
    int pos = atomicAdd(&g_cur[e], 1);
    g_tok[pos] = i / KK;
    g_wt[pos] = g_w[i];
}

// ---------------------------------------------------------------------------
// Final: out = rmsnorm(h1 + shared + routed)
// ---------------------------------------------------------------------------
__global__ void k_final(float* __restrict__ out)
{
    __shared__ float ys[HH];
    __shared__ float red[256];
    const int r = blockIdx.x;
    float ss = 0.f;
    for (int i = threadIdx.x; i < HH; i += 256) {
        size_t p = (size_t)r * HH + i;
        float v = g_h1[p] + g_shared[p] + g_routed[p];
        ys[i] = v;
        ss += v * v;
    }
    red[threadIdx.x] = ss;
    __syncthreads();
    for (int s = 128; s > 0; s >>= 1) {
        if (threadIdx.x < s) red[threadIdx.x] += red[threadIdx.x + s];
        __syncthreads();
    }
    float scale = rsqrtf(red[0] / (float)HH + EPSF);
    for (int i = threadIdx.x; i < HH; i += 256)
        out[(size_t)r * HH + i] = ys[i] * scale;
}

__global__ void k_aux(float* __restrict__ dst)
{
    float f_i[EE], P_i[EE];
    for (int e = 0; e < EE; ++e) {
        f_i[e] = (float)g_cnt[e] / ((float)TOTSEL + 1e-10f);
        P_i[e] = g_probsum[e] / (float)TT;
    }
    float eb = 0.f;
    for (int e = 0; e < EE; ++e) eb += f_i[e] * P_i[e];
    float expert_bal = fminf(eb * 0.003f, 10.f);

    float db = 0.f, cb = 0.f;
    for (int d = 0; d < DD; ++d) {
        float df = 0.f, dP = 0.f;
        for (int j = 0; j < EPD; ++j) { df += f_i[4*d + j]; dP += P_i[4*d + j]; }
        df *= 0.25f;
        db += df * dP;
        float fc = g_devhit[d] / ((float)(TT * KDD) + 1e-10f);
        cb += fc * dP;
    }
    float device_bal = fminf(db * 0.05f, 10.f);
    float comm_bal   = fminf(cb * 0.02f, 10.f);
    *dst = expert_bal + device_bal + comm_bal;
}

// ---------------------------------------------------------------------------
// Launch
// ---------------------------------------------------------------------------
extern "C" void kernel_launch(void* const* d_in, const int* in_sizes, int n_in,
                              void* d_out, int out_size)
{
    const float* x     = (const float*)d_in[0];
    const float* Wqkv  = (const float*)d_in[1];
    const float* Wo    = (const float*)d_in[2];
    const float* Wgu_s = (const float*)d_in[3];
    const float* Wd_s  = (const float*)d_in[4];
    const float* Wr    = (const float*)d_in[5];
    const float* Wgu   = (const float*)d_in[6];
    const float* Wd    = (const float*)d_in[7];
    float* out = (float*)d_out;

    k_zero<<<(TT * HH + 255) / 256, 256>>>();

    // QKV: x[1024,1024] @ Wqkv[1024,3072] -> g_qkv
    mma_gemm<0, false><<<dim3(24, 8, 1), 256>>>(x, -1, BUF_QKV, Wqkv, 0, HH, 3 * HH);

    k_attn<<<dim3(SS / 4, NHH, BB), 128>>>();

    // Wo: g_attn @ Wo[1024,1024] -> g_attno
    mma_gemm<0, false><<<dim3(8, 8, 1), 256>>>(nullptr, BUF_ATTN, BUF_ATTNO, Wo, 0, HH, HH);

    k_addrms<<<TT, 256>>>(x);

    // Shared expert 0
    mma_gemm<0, false><<<dim3(24, 8, 1), 256>>>(nullptr, BUF_H1, BUF_GU, Wgu_s, 0, HH, GU);
    k_act<<<1024, 256>>>(TT);
    mma_gemm<0, false><<<dim3(8, 8, 1), 256>>>(nullptr, BUF_ACT, BUF_SHARED, Wd_s, 0, INTER, HH);

    // Shared expert 1 (accumulate)
    mma_gemm<0, false><<<dim3(24, 8, 1), 256>>>(nullptr, BUF_H1, BUF_GU, Wgu_s + (size_t)HH * GU, 0, HH, GU);
    k_act<<<1024, 256>>>(TT);
    mma_gemm<0, true ><<<dim3(8, 8, 1), 256>>>(nullptr, BUF_ACT, BUF_SHARED, Wd_s + (size_t)INTER * HH, 0, INTER, HH);

    // Routing
    k_route<<<TT, 32>>>(Wr);
    k_scan<<<1, 1>>>();
    k_build<<<TOTSEL / 256, 256>>>();

    // Routed experts (grouped, gathered)
    mma_gemm<1, false><<<dim3(24, 8, EE), 256>>>(nullptr, -1, -1, Wgu, (long long)HH * GU, HH, GU);
    k_act<<<4096, 256>>>(TOTSEL);
    mma_gemm<2, false><<<dim3(8, 8, EE), 256>>>(nullptr, -1, -1, Wd, (long long)INTER * HH, INTER, HH);

    k_final<<<TT, 256>>>(out);

    if (out_size > TT * HH)
        k_aux<<<1, 1>>>(out + TT * HH);
}

// round 13
// speedup vs baseline: 2.2807x; 1.2206x over previous
#include <cuda_runtime.h>
#include <cuda_bf16.h>
#include <stdint.h>
#include <math.h>

// ---------------------------------------------------------------------------
// Problem constants
// ---------------------------------------------------------------------------
#define BB 2
#define SS 512
#define HH 1024
#define NHH 16
#define HD 64
#define TT (BB*SS)          // 1024 tokens
#define EE 32               // experts
#define DD 8                // devices
#define KK 6                // top-k experts
#define KDD 3               // top devices
#define EPD (EE/DD)         // 4 experts per device
#define INTER 1536
#define GU (2*INTER)        // 3072
#define EPSF 1e-5f
#define TOTSEL (TT*KK)      // 6144

// ---------------------------------------------------------------------------
// Scratch (static device globals; accessed ONLY by device-code symbol refs)
// ---------------------------------------------------------------------------
__device__ float g_qkv   [TT * 3 * HH];
__device__ float g_attn  [TT * HH];
__device__ float g_attno [TT * HH];
__device__ float g_h1    [TT * HH];
__device__ float g_gu    [TOTSEL * GU];
__device__ float g_act   [TOTSEL * INTER];
__device__ float g_shared[TT * HH];
__device__ float g_routed[TT * HH];

__device__ int   g_idx   [TT * KK];
__device__ float g_w     [TT * KK];
__device__ int   g_cnt   [EE];
__device__ int   g_off   [EE];
__device__ int   g_cur   [EE];
__device__ int   g_tok   [TOTSEL];
__device__ float g_wt    [TOTSEL];
__device__ float g_probsum[EE];
__device__ float g_devhit [DD];

#define BUF_QKV    0
#define BUF_ATTN   1
#define BUF_ATTNO  2
#define BUF_H1     3
#define BUF_GU     4
#define BUF_ACT    5
#define BUF_SHARED 6
__device__ __forceinline__ float* devbuf(int id) {
    switch (id) {
        case BUF_QKV:    return g_qkv;
        case BUF_ATTN:   return g_attn;
        case BUF_ATTNO:  return g_attno;
        case BUF_H1:     return g_h1;
        case BUF_GU:     return g_gu;
        case BUF_ACT:    return g_act;
        case BUF_SHARED: return g_shared;
        default:         return g_routed;
    }
}

// ---------------------------------------------------------------------------
// PTX helpers (base ISA: ldmatrix + mma.sync; tcgen05 unavailable at the
// compute_103 PTX target this harness compiles with)
// ---------------------------------------------------------------------------
__device__ __forceinline__ uint32_t smem_u32(const void* p) {
    uint32_t a;
    asm("{ .reg .u64 t; cvta.to.shared.u64 t, %1; cvt.u32.u64 %0, t; }" : "=r"(a) : "l"(p));
    return a;
}
__device__ __forceinline__ void ldsm_x4(uint32_t& r0, uint32_t& r1, uint32_t& r2, uint32_t& r3,
                                        uint32_t addr) {
    asm volatile("ldmatrix.sync.aligned.m8n8.x4.shared.b16 {%0,%1,%2,%3}, [%4];"
                 : "=r"(r0), "=r"(r1), "=r"(r2), "=r"(r3) : "r"(addr));
}
__device__ __forceinline__ void ldsm_x4_t(uint32_t& r0, uint32_t& r1, uint32_t& r2, uint32_t& r3,
                                          uint32_t addr) {
    asm volatile("ldmatrix.sync.aligned.m8n8.x4.trans.shared.b16 {%0,%1,%2,%3}, [%4];"
                 : "=r"(r0), "=r"(r1), "=r"(r2), "=r"(r3) : "r"(addr));
}
__device__ __forceinline__ void mma_bf16(float* c, const uint32_t* a, const uint32_t* b) {
    asm volatile("mma.sync.aligned.m16n8k16.row.col.f32.bf16.bf16.f32 "
                 "{%0,%1,%2,%3}, {%4,%5,%6,%7}, {%8,%9}, {%0,%1,%2,%3};"
                 : "+f"(c[0]), "+f"(c[1]), "+f"(c[2]), "+f"(c[3])
                 : "r"(a[0]), "r"(a[1]), "r"(a[2]), "r"(a[3]), "r"(b[0]), "r"(b[1]));
}
// pack (lo_elem, hi_elem) -> bf16x2; first PTX source goes to the HIGH half
__device__ __forceinline__ uint32_t pk_bf16x2(float lo, float hi) {
    uint32_t r;
    asm("cvt.rn.bf16x2.f32 %0, %1, %2;" : "=r"(r) : "f"(hi), "f"(lo));
    return r;
}
__device__ __forceinline__ float bf16_round(float x) {
    return __bfloat162float(__float2bfloat16(x));
}

// ---------------------------------------------------------------------------
// bf16-split tensor-core GEMM:  C[M,N] = A[M,K] @ W[K,N]  (fp32 in/out)
//   A@B ~= Ahi*Bhi + Alo*Bhi + Ahi*Blo  (fp32 accumulate, err ~2^-18)
// MODE 0: plain  | MODE 1: gather (rows via g_tok)  | MODE 2: weighted scatter
// Tile 64x128x32, 256 threads (8 warps as 4x2), warp = 16x64, 2 CTAs/SM.
// ---------------------------------------------------------------------------
#define BM 64
#define BN 128
#define BK 32
#define ASTR (BK + 8)       // 40
#define BSTR (BN + 8)       // 136

template<int MODE, bool ACCUM>
__global__ __launch_bounds__(256, 2)
void mma_gemm(const float* __restrict__ Aext, int Aid, int Cid,
              const float* __restrict__ W, long long Wstride,
              int K, int N)
{
    __shared__ __align__(16) __nv_bfloat16 As_hi[BM][ASTR];
    __shared__ __align__(16) __nv_bfloat16 As_lo[BM][ASTR];
    __shared__ __align__(16) __nv_bfloat16 Bs_hi[BK][BSTR];
    __shared__ __align__(16) __nv_bfloat16 Bs_lo[BK][BSTR];

    const int tid  = threadIdx.x;
    const int lane = tid & 31;
    const int warp = tid >> 5;
    const int wm = warp >> 1;          // 0..3
    const int wn = warp & 1;           // 0..1
    const int m0 = blockIdx.y * BM;
    const int n0 = blockIdx.x * BN;
    const int z  = blockIdx.z;

    int cnt = 0, off = 0;
    if (MODE != 0) {
        cnt = g_cnt[z];
        off = g_off[z];
        if (m0 >= cnt) return;
    }
    const float* Wb = W + (size_t)z * (size_t)Wstride;
    const float* Abase = (MODE == 0) ? (Aext ? Aext : devbuf(Aid)) : nullptr;

    // fill coordinates: A = 2 chunks, B = 4 chunks of float4 per thread
    int arow[2], akc[2], brow[4], bnc[4];
    const float* aptr[2];
    #pragma unroll
    for (int i = 0; i < 2; ++i) {
        int ca = tid + i * 256;        // 0..511 over 64x8 float4 chunks
        arow[i] = ca >> 3;
        akc[i]  = (ca & 7) * 4;
        int lr = m0 + arow[i];
        if (MODE == 0)      aptr[i] = Abase + (size_t)lr * (size_t)K;
        else if (MODE == 1) aptr[i] = (lr < cnt) ? g_h1 + (size_t)g_tok[off + lr] * HH : nullptr;
        else                aptr[i] = (lr < cnt) ? g_act + (size_t)(off + lr) * (size_t)K : nullptr;
    }
    #pragma unroll
    for (int i = 0; i < 4; ++i) {
        int ca = tid + i * 256;        // 0..1023 over 32x32 float4 chunks
        brow[i] = ca >> 5;
        bnc[i]  = (ca & 31) * 4;
    }

    float acc[8][4];
    #pragma unroll
    for (int j = 0; j < 8; ++j)
        #pragma unroll
        for (int c = 0; c < 4; ++c) acc[j][c] = 0.f;

    const int niter = K / BK;
    for (int it = 0; it < niter; ++it) {
        const int k0 = it * BK;
        // ---- fill A (hi/lo) ----
        #pragma unroll
        for (int i = 0; i < 2; ++i) {
            float4 av = aptr[i] ? *(const float4*)(aptr[i] + k0 + akc[i])
                                : make_float4(0.f,0.f,0.f,0.f);
            float hx = bf16_round(av.x), hy = bf16_round(av.y);
            float hz = bf16_round(av.z), hw = bf16_round(av.w);
            *(uint2*)&As_hi[arow[i]][akc[i]] =
                make_uint2(pk_bf16x2(av.x, av.y), pk_bf16x2(av.z, av.w));
            *(uint2*)&As_lo[arow[i]][akc[i]] =
                make_uint2(pk_bf16x2(av.x - hx, av.y - hy), pk_bf16x2(av.z - hz, av.w - hw));
        }
        // ---- fill B (hi/lo) ----
        #pragma unroll
        for (int i = 0; i < 4; ++i) {
            float4 bv = *(const float4*)(Wb + (size_t)(k0 + brow[i]) * (size_t)N + n0 + bnc[i]);
            float gx = bf16_round(bv.x), gy = bf16_round(bv.y);
            float gz = bf16_round(bv.z), gw = bf16_round(bv.w);
            *(uint2*)&Bs_hi[brow[i]][bnc[i]] =
                make_uint2(pk_bf16x2(bv.x, bv.y), pk_bf16x2(bv.z, bv.w));
            *(uint2*)&Bs_lo[brow[i]][bnc[i]] =
                make_uint2(pk_bf16x2(bv.x - gx, bv.y - gy), pk_bf16x2(bv.z - gz, bv.w - gw));
        }
        __syncthreads();

        // ---- compute: 2 k16 steps ----
        #pragma unroll
        for (int s = 0; s < 2; ++s) {
            uint32_t ah[4], al[4], bh[4][4], bl[4][4];
            const int ar = lane & 15;
            const int ac = s * 16 + (lane >> 4) * 8;
            ldsm_x4(ah[0], ah[1], ah[2], ah[3], smem_u32(&As_hi[wm * 16 + ar][ac]));
            ldsm_x4(al[0], al[1], al[2], al[3], smem_u32(&As_lo[wm * 16 + ar][ac]));
            const int br = s * 16 + (lane & 15);
            #pragma unroll
            for (int g = 0; g < 4; ++g) {
                int bc = wn * 64 + g * 16 + (lane >> 4) * 8;
                ldsm_x4_t(bh[g][0], bh[g][1], bh[g][2], bh[g][3], smem_u32(&Bs_hi[br][bc]));
                ldsm_x4_t(bl[g][0], bl[g][1], bl[g][2], bl[g][3], smem_u32(&Bs_lo[br][bc]));
            }
            #pragma unroll
            for (int j = 0; j < 8; ++j) {
                const int g = j >> 1;
                const int sel = (j & 1) * 2;
                mma_bf16(acc[j], ah, &bh[g][sel]);   // hi*hi
                mma_bf16(acc[j], al, &bh[g][sel]);   // lo*hi
                mma_bf16(acc[j], ah, &bl[g][sel]);   // hi*lo
            }
        }
        __syncthreads();
    }

    // ---- epilogue ----
    const int gq = lane >> 2;          // 0..7
    const int tq = lane & 3;           // 0..3
    const int rr0 = wm * 16 + gq;
    const int rr1 = rr0 + 8;
    #pragma unroll
    for (int j = 0; j < 8; ++j) {
        const int col = n0 + wn * 64 + j * 8 + tq * 2;
        float d0 = acc[j][0], d1 = acc[j][1], d2 = acc[j][2], d3 = acc[j][3];
        if (MODE == 0) {
            float* C = devbuf(Cid);
            float2* p0 = (float2*)&C[(size_t)(m0 + rr0) * (size_t)N + col];
            float2* p1 = (float2*)&C[(size_t)(m0 + rr1) * (size_t)N + col];
            if (ACCUM) {
                float2 o0 = *p0, o1 = *p1;
                *p0 = make_float2(o0.x + d0, o0.y + d1);
                *p1 = make_float2(o1.x + d2, o1.y + d3);
            } else {
                *p0 = make_float2(d0, d1);
                *p1 = make_float2(d2, d3);
            }
        } else if (MODE == 1) {
            if (m0 + rr0 < cnt)
                *(float2*)&g_gu[(size_t)(off + m0 + rr0) * (size_t)N + col] = make_float2(d0, d1);
            if (m0 + rr1 < cnt)
                *(float2*)&g_gu[(size_t)(off + m0 + rr1) * (size_t)N + col] = make_float2(d2, d3);
        } else {
            if (m0 + rr0 < cnt) {
                int token = g_tok[off + m0 + rr0];
                float wt  = g_wt[off + m0 + rr0];
                atomicAdd(&g_routed[(size_t)token * HH + col],     wt * d0);
                atomicAdd(&g_routed[(size_t)token * HH + col + 1], wt * d1);
            }
            if (m0 + rr1 < cnt) {
                int token = g_tok[off + m0 + rr1];
                float wt  = g_wt[off + m0 + rr1];
                atomicAdd(&g_routed[(size_t)token * HH + col],     wt * d2);
                atomicAdd(&g_routed[(size_t)token * HH + col + 1], wt * d3);
            }
        }
    }
}

// ---------------------------------------------------------------------------
// Zero-init (graph replays)
// ---------------------------------------------------------------------------
__global__ void k_zero() {
    int i = blockIdx.x * blockDim.x + threadIdx.x;
    if (i < TT * HH) g_routed[i] = 0.f;
    if (i < EE) { g_cnt[i] = 0; g_probsum[i] = 0.f; }
    if (i < DD) g_devhit[i] = 0.f;
}

// ---------------------------------------------------------------------------
// Attention v2: block = 4 warps / 16 queries for one (b,h).
// K/V tiles staged in smem (shared by all warps); lane owns 2 keys in the
// score phase and 2 output dims (l, l+32) in the PV phase. No shuffles in
// hot loops; one 5-shfl softmax reduction per query.
// smem (floats): Kt[64*65] | qs[16*64] | sc[16*512]
// ---------------------------------------------------------------------------
#define AQB 16
#define KTS 65
#define A_KT 0
#define A_QS (64 * KTS)                 // 4160
#define A_QSN (A_QS + AQB * 64)         // 5184
#define ATT_SMEM ((A_QSN + AQB * SS) * 4)

__global__ void k_attn2()
{
    extern __shared__ float sm[];
    const int tid = threadIdx.x, lane = tid & 31, w = tid >> 5;
    const int q0 = blockIdx.x * AQB;
    const int h = blockIdx.y, b = blockIdx.z;
    const size_t base = (size_t)b * SS * 3 * HH + (size_t)h * HD;
    const int wq = w * 4;

    // load Q block [16 x 64]
    for (int i = tid; i < AQB * 16; i += 128) {
        int qi = i >> 4, dc = (i & 15) * 4;
        *(float4*)&sm[A_QS + qi * 64 + dc] =
            *(const float4*)(g_qkv + base + (size_t)(q0 + qi) * (3 * HH) + dc);
    }

    // ---- scores ----
    for (int t = 0; t < SS / 64; ++t) {
        __syncthreads();   // Kt reuse guard (and qs visibility on t=0)
        for (int i = tid; i < 64 * 16; i += 128) {
            int kr = i >> 4, dc = (i & 15) * 4;
            float4 kv = *(const float4*)(g_qkv + base + HH +
                                         (size_t)(t * 64 + kr) * (3 * HH) + dc);
            float* d = &sm[A_KT + kr * KTS + dc];
            d[0] = kv.x; d[1] = kv.y; d[2] = kv.z; d[3] = kv.w;
        }
        __syncthreads();
        float s0[4] = {0,0,0,0}, s1[4] = {0,0,0,0};
        #pragma unroll 4
        for (int d4 = 0; d4 < 16; ++d4) {
            const int d = d4 * 4;
            const float* k0p = &sm[A_KT + lane * KTS + d];
            const float* k1p = &sm[A_KT + (lane + 32) * KTS + d];
            float k00 = k0p[0], k01 = k0p[1], k02 = k0p[2], k03 = k0p[3];
            float k10 = k1p[0], k11 = k1p[1], k12 = k1p[2], k13 = k1p[3];
            #pragma unroll
            for (int j = 0; j < 4; ++j) {
                float4 qv = *(float4*)&sm[A_QS + (wq + j) * 64 + d];
                s0[j] += qv.x * k00 + qv.y * k01 + qv.z * k02 + qv.w * k03;
                s1[j] += qv.x * k10 + qv.y * k11 + qv.z * k12 + qv.w * k13;
            }
        }
        #pragma unroll
        for (int j = 0; j < 4; ++j) {
            sm[A_QSN + (wq + j) * SS + t * 64 + lane]      = s0[j] * 0.125f;
            sm[A_QSN + (wq + j) * SS + t * 64 + lane + 32] = s1[j] * 0.125f;
        }
    }
    __syncthreads();

    // ---- softmax (per warp, own 4 queries) ----
    float inv[4];
    #pragma unroll
    for (int j = 0; j < 4; ++j) {
        float* row = &sm[A_QSN + (wq + j) * SS];
        float m = -INFINITY;
        for (int i = lane; i < SS; i += 32) m = fmaxf(m, row[i]);
        #pragma unroll
        for (int o = 16; o > 0; o >>= 1) m = fmaxf(m, __shfl_xor_sync(0xffffffffu, m, o));
        float sum = 0.f;
        for (int i = lane; i < SS; i += 32) {
            float p = expf(row[i] - m);
            row[i] = p;
            sum += p;
        }
        #pragma unroll
        for (int o = 16; o > 0; o >>= 1) sum += __shfl_xor_sync(0xffffffffu, sum, o);
        inv[j] = 1.f / sum;
    }

    // ---- PV ----
    float2 acc[4] = {{0.f,0.f},{0.f,0.f},{0.f,0.f},{0.f,0.f}};
    for (int t = 0; t < SS / 64; ++t) {
        __syncthreads();   // all warps past previous Kt use
        for (int i = tid; i < 64 * 16; i += 128) {
            int kr = i >> 4, dc = (i & 15) * 4;
            float4 vv = *(const float4*)(g_qkv + base + 2 * HH +
                                         (size_t)(t * 64 + kr) * (3 * HH) + dc);
            float* d = &sm[A_KT + kr * KTS + dc];
            d[0] = vv.x; d[1] = vv.y; d[2] = vv.z; d[3] = vv.w;
        }
        __syncthreads();
        #pragma unroll 4
        for (int kk = 0; kk < 64; ++kk) {
            float vx = sm[A_KT + kk * KTS + lane];
            float vy = sm[A_KT + kk * KTS + lane + 32];
            #pragma unroll
            for (int j = 0; j < 4; ++j) {
                float pp = sm[A_QSN + (wq + j) * SS + t * 64 + kk];
                acc[j].x += pp * vx;
                acc[j].y += pp * vy;
            }
        }
    }

    #pragma unroll
    for (int j = 0; j < 4; ++j) {
        float* o = g_attn + (size_t)(b * SS + q0 + wq + j) * HH + h * HD;
        o[lane]      = acc[j].x * inv[j];
        o[lane + 32] = acc[j].y * inv[j];
    }
}

// ---------------------------------------------------------------------------
// h1 = rmsnorm(x + attno)
// ---------------------------------------------------------------------------
__global__ void k_addrms(const float* __restrict__ x)
{
    __shared__ float ys[HH];
    __shared__ float red[256];
    const int r = blockIdx.x;
    float ss = 0.f;
    for (int i = threadIdx.x; i < HH; i += 256) {
        float v = x[(size_t)r * HH + i] + g_attno[(size_t)r * HH + i];
        ys[i] = v;
        ss += v * v;
    }
    red[threadIdx.x] = ss;
    __syncthreads();
    for (int s = 128; s > 0; s >>= 1) {
        if (threadIdx.x < s) red[threadIdx.x] += red[threadIdx.x + s];
        __syncthreads();
    }
    float scale = rsqrtf(red[0] / (float)HH + EPSF);
    for (int i = threadIdx.x; i < HH; i += 256)
        g_h1[(size_t)r * HH + i] = ys[i] * scale;
}

// ---------------------------------------------------------------------------
// SwiGLU activation
// ---------------------------------------------------------------------------
__global__ void k_act(int rows)
{
    const long long n = (long long)rows * INTER;
    for (long long i = (long long)blockIdx.x * blockDim.x + threadIdx.x;
         i < n; i += (long long)gridDim.x * blockDim.x) {
        long long r = i / INTER;
        long long j = i % INTER;
        float g = g_gu[r * GU + j];
        float u = g_gu[r * GU + INTER + j];
        float s = g / (1.f + expf(-g));
        g_act[i] = s * u;
    }
}

// ---------------------------------------------------------------------------
// Router: one warp per token.
// ---------------------------------------------------------------------------
__global__ void k_route(const float* __restrict__ Wr)
{
    __shared__ float xr[HH];
    __shared__ float logit_s[EE];
    __shared__ float probs[EE];
    const int t = blockIdx.x;
    const int lane = threadIdx.x;

    for (int i = lane; i < HH; i += 32) xr[i] = g_h1[(size_t)t * HH + i];
    __syncwarp();
    float acc = 0.f;
    for (int hh = 0; hh < HH; ++hh)
        acc = fmaf(xr[hh], Wr[(size_t)hh * EE + lane], acc);
    logit_s[lane] = acc;
    __syncwarp();

    if (lane == 0) {
        float m = -INFINITY;
        for (int e = 0; e < EE; ++e) m = fmaxf(m, logit_s[e]);
        float s = 0.f;
        for (int e = 0; e < EE; ++e) { float p = expf(logit_s[e] - m); probs[e] = p; s += p; }
        float inv = 1.f / s;
        for (int e = 0; e < EE; ++e) probs[e] *= inv;

        float dev[DD];
        for (int d = 0; d < DD; ++d)
            dev[d] = probs[4*d] + probs[4*d+1] + probs[4*d+2] + probs[4*d+3];
        bool devsel[DD];
        for (int d = 0; d < DD; ++d) devsel[d] = false;
        for (int rr = 0; rr < KDD; ++rr) {
            float best = -INFINITY; int bi = -1;
            for (int d = 0; d < DD; ++d)
                if (!devsel[d] && dev[d] > best) { best = dev[d]; bi = d; }
            devsel[bi] = true;
        }
        int idx6[KK]; float w6[KK];
        bool taken[EE];
        for (int e = 0; e < EE; ++e) taken[e] = false;
        for (int rr = 0; rr < KK; ++rr) {
            float best = -INFINITY; int bi = -1;
            for (int e = 0; e < EE; ++e)
                if (devsel[e >> 2] && !taken[e] && probs[e] > best) { best = probs[e]; bi = e; }
            taken[bi] = true; idx6[rr] = bi; w6[rr] = best;
        }
        float wm = -INFINITY;
        for (int rr = 0; rr < KK; ++rr) wm = fmaxf(wm, w6[rr]);
        float ws = 0.f;
        for (int rr = 0; rr < KK; ++rr) { w6[rr] = expf(w6[rr] - wm); ws += w6[rr]; }
        float winv = 1.f / ws;
        for (int rr = 0; rr < KK; ++rr) {
            w6[rr] *= winv;
            g_idx[t * KK + rr] = idx6[rr];
            g_w[t * KK + rr] = w6[rr];
            atomicAdd(&g_cnt[idx6[rr]], 1);
        }
        bool hit[DD];
        for (int d = 0; d < DD; ++d) hit[d] = false;
        for (int rr = 0; rr < KK; ++rr) hit[idx6[rr] >> 2] = true;
        for (int d = 0; d < DD; ++d)
            if (hit[d]) atomicAdd(&g_devhit[d], 1.0f);
    }
    __syncwarp();
    atomicAdd(&g_probsum[lane], probs[lane]);
}

__global__ void k_scan()
{
    int acc = 0;
    for (int e = 0; e < EE; ++e) {
        g_off[e] = acc;
        g_cur[e] = acc;
        acc += g_cnt[e];
    }
}

__global__ void k_build()
{
    int i = blockIdx.x * blockDim.x + threadIdx.x;
    if (i >= TOTSEL) return;
    int e = g_idx[i];
    int pos = atomicAdd(&g_cur[e], 1);
    g_tok[pos] = i / KK;
    g_wt[pos] = g_w[i];
}

// ---------------------------------------------------------------------------
// Final: out = rmsnorm(h1 + shared + routed)
// ---------------------------------------------------------------------------
__global__ void k_final(float* __restrict__ out)
{
    __shared__ float ys[HH];
    __shared__ float red[256];
    const int r = blockIdx.x;
    float ss = 0.f;
    for (int i = threadIdx.x; i < HH; i += 256) {
        size_t p = (size_t)r * HH + i;
        float v = g_h1[p] + g_shared[p] + g_routed[p];
        ys[i] = v;
        ss += v * v;
    }
    red[threadIdx.x] = ss;
    __syncthreads();
    for (int s = 128; s > 0; s >>= 1) {
        if (threadIdx.x < s) red[threadIdx.x] += red[threadIdx.x + s];
        __syncthreads();
    }
    float scale = rsqrtf(red[0] / (float)HH + EPSF);
    for (int i = threadIdx.x; i < HH; i += 256)
        out[(size_t)r * HH + i] = ys[i] * scale;
}

__global__ void k_aux(float* __restrict__ dst)
{
    float f_i[EE], P_i[EE];
    for (int e = 0; e < EE; ++e) {
        f_i[e] = (float)g_cnt[e] / ((float)TOTSEL + 1e-10f);
        P_i[e] = g_probsum[e] / (float)TT;
    }
    float eb = 0.f;
    for (int e = 0; e < EE; ++e) eb += f_i[e] * P_i[e];
    float expert_bal = fminf(eb * 0.003f, 10.f);

    float db = 0.f, cb = 0.f;
    for (int d = 0; d < DD; ++d) {
        float df = 0.f, dP = 0.f;
        for (int j = 0; j < EPD; ++j) { df += f_i[4*d + j]; dP += P_i[4*d + j]; }
        df *= 0.25f;
        db += df * dP;
        float fc = g_devhit[d] / ((float)(TT * KDD) + 1e-10f);
        cb += fc * dP;
    }
    float device_bal = fminf(db * 0.05f, 10.f);
    float comm_bal   = fminf(cb * 0.02f, 10.f);
    *dst = expert_bal + device_bal + comm_bal;
}

// ---------------------------------------------------------------------------
// Launch
// ---------------------------------------------------------------------------
extern "C" void kernel_launch(void* const* d_in, const int* in_sizes, int n_in,
                              void* d_out, int out_size)
{
    const float* x     = (const float*)d_in[0];
    const float* Wqkv  = (const float*)d_in[1];
    const float* Wo    = (const float*)d_in[2];
    const float* Wgu_s = (const float*)d_in[3];
    const float* Wd_s  = (const float*)d_in[4];
    const float* Wr    = (const float*)d_in[5];
    const float* Wgu   = (const float*)d_in[6];
    const float* Wd    = (const float*)d_in[7];
    float* out = (float*)d_out;

    cudaFuncSetAttribute(k_attn2, cudaFuncAttributeMaxDynamicSharedMemorySize, ATT_SMEM);

    k_zero<<<(TT * HH + 255) / 256, 256>>>();

    // QKV: x[1024,1024] @ Wqkv[1024,3072] -> g_qkv
    mma_gemm<0, false><<<dim3(24, 16, 1), 256>>>(x, -1, BUF_QKV, Wqkv, 0, HH, 3 * HH);

    k_attn2<<<dim3(SS / AQB, NHH, BB), 128, ATT_SMEM>>>();

    // Wo: g_attn @ Wo[1024,1024] -> g_attno
    mma_gemm<0, false><<<dim3(8, 16, 1), 256>>>(nullptr, BUF_ATTN, BUF_ATTNO, Wo, 0, HH, HH);

    k_addrms<<<TT, 256>>>(x);

    // Shared expert 0
    mma_gemm<0, false><<<dim3(24, 16, 1), 256>>>(nullptr, BUF_H1, BUF_GU, Wgu_s, 0, HH, GU);
    k_act<<<1024, 256>>>(TT);
    mma_gemm<0, false><<<dim3(8, 16, 1), 256>>>(nullptr, BUF_ACT, BUF_SHARED, Wd_s, 0, INTER, HH);

    // Shared expert 1 (accumulate)
    mma_gemm<0, false><<<dim3(24, 16, 1), 256>>>(nullptr, BUF_H1, BUF_GU, Wgu_s + (size_t)HH * GU, 0, HH, GU);
    k_act<<<1024, 256>>>(TT);
    mma_gemm<0, true ><<<dim3(8, 16, 1), 256>>>(nullptr, BUF_ACT, BUF_SHARED, Wd_s + (size_t)INTER * HH, 0, INTER, HH);

    // Routing
    k_route<<<TT, 32>>>(Wr);
    k_scan<<<1, 1>>>();
    k_build<<<TOTSEL / 256, 256>>>();

    // Routed experts (grouped, gathered)
    mma_gemm<1, false><<<dim3(24, 16, EE), 256>>>(nullptr, -1, -1, Wgu, (long long)HH * GU, HH, GU);
    k_act<<<4096, 256>>>(TOTSEL);
    mma_gemm<2, false><<<dim3(8, 16, EE), 256>>>(nullptr, -1, -1, Wd, (long long)INTER * HH, INTER, HH);

    k_final<<<TT, 256>>>(out);

    if (out_size > TT * HH)
        k_aux<<<1, 1>>>(out + TT * HH);
}